// round 1
// baseline (speedup 1.0000x reference)
#include <cuda_runtime.h>
#include <math.h>

#define NN 100000
#define DD 128
#define EE 1600000
#define BB 100000

// ---------------- scratch (no allocations allowed) ----------------
__device__ float  g_tmp[(size_t)NN * DD];   // X@W / H@W scratch
__device__ float  g_h[(size_t)NN * DD];     // layer output / encoding
__device__ float  g_dinv[NN];
__device__ int    g_deg[NN];
__device__ double g_acc[8];                 // [bce_s, cu_s, ci_s, bce_t, cu_t, ci_t]

// ---------------- small kernels ----------------
__global__ void k_zero(int zero_acc) {
    int i = blockIdx.x * blockDim.x + threadIdx.x;
    if (i < NN) g_deg[i] = 0;
    if (zero_acc && i < 8) g_acc[i] = 0.0;
}

__global__ void k_deg(const int* __restrict__ dst) {
    int e = blockIdx.x * blockDim.x + threadIdx.x;
    if (e < EE) atomicAdd(&g_deg[dst[e]], 1);
}

__global__ void k_dinv() {
    int i = blockIdx.x * blockDim.x + threadIdx.x;
    if (i < NN) g_dinv[i] = rsqrtf((float)g_deg[i] + 1.0f);  // +1 = self loop
}

// out[i][:] = bias + dinv[i]^2 * tmp[i][:]   (bias + self-loop term)
__global__ void k_init(const float* __restrict__ tmp, const float* __restrict__ bias,
                       float* __restrict__ out) {
    int i = blockIdx.x * blockDim.x + threadIdx.x;   // float4 index
    if (i < NN * 32) {
        int row = i >> 5;
        int j = i & 31;
        float d = g_dinv[row];
        float d2 = d * d;
        float4 t = ((const float4*)tmp)[i];
        float4 b = ((const float4*)bias)[j];
        float4 o;
        o.x = fmaf(d2, t.x, b.x);
        o.y = fmaf(d2, t.y, b.y);
        o.z = fmaf(d2, t.z, b.z);
        o.w = fmaf(d2, t.w, b.w);
        ((float4*)out)[i] = o;
    }
}

// one warp per edge: out[dst] += dinv[src]*dinv[dst] * tmp[src]
__global__ void k_scatter(const float* __restrict__ tmp,
                          const int* __restrict__ esrc, const int* __restrict__ edst,
                          float* __restrict__ out) {
    int w = (blockIdx.x * blockDim.x + threadIdx.x) >> 5;
    int lane = threadIdx.x & 31;
    if (w >= EE) return;
    int s = esrc[w];
    int d = edst[w];
    float nrm = g_dinv[s] * g_dinv[d];
    float4 v = ((const float4*)tmp)[s * 32 + lane];
    v.x *= nrm; v.y *= nrm; v.z *= nrm; v.w *= nrm;
    float* p = &out[(size_t)d * DD + lane * 4];
    asm volatile("red.global.add.v4.f32 [%0], {%1, %2, %3, %4};"
                 :: "l"(p), "f"(v.x), "f"(v.y), "f"(v.z), "f"(v.w) : "memory");
}

// ---------------- GEMM: C[N,128] = (relu?)A[N,128] @ W[128,128] ----------------
template <bool RELU>
__global__ __launch_bounds__(256, 2) void k_gemm(const float* __restrict__ A,
                                                 const float* __restrict__ W,
                                                 float* __restrict__ C) {
    __shared__ float sW[16 * 128];   // k-chunk of W
    __shared__ float sA[16 * 132];   // transposed A chunk [k][row], padded stride
    int tid = threadIdx.x;
    int r0 = blockIdx.x * 128;
    int tx = tid & 15, ty = tid >> 4;

    float acc[8][8];
#pragma unroll
    for (int m = 0; m < 8; m++)
#pragma unroll
        for (int n = 0; n < 8; n++) acc[m][n] = 0.f;

    for (int kk = 0; kk < DD; kk += 16) {
        __syncthreads();
        // load A chunk: 128 rows x 16 k, transposed into sA[k][row]
#pragma unroll
        for (int i = 0; i < 2; i++) {
            int q = tid + 256 * i;          // 0..511
            int row = q >> 2;               // 0..127
            int c4 = (q & 3) << 2;          // 0,4,8,12
            int gr = r0 + row;
            float4 a = make_float4(0.f, 0.f, 0.f, 0.f);
            if (gr < NN) a = *(const float4*)&A[(size_t)gr * DD + kk + c4];
            if (RELU) {
                a.x = fmaxf(a.x, 0.f); a.y = fmaxf(a.y, 0.f);
                a.z = fmaxf(a.z, 0.f); a.w = fmaxf(a.w, 0.f);
            }
            sA[(c4 + 0) * 132 + row] = a.x;
            sA[(c4 + 1) * 132 + row] = a.y;
            sA[(c4 + 2) * 132 + row] = a.z;
            sA[(c4 + 3) * 132 + row] = a.w;
        }
        // load W chunk: rows kk..kk+15
#pragma unroll
        for (int i = 0; i < 2; i++) {
            int q = tid + 256 * i;          // 0..511
            int kr = q >> 5;                // 0..15
            int c4 = (q & 31) << 2;         // 0..124
            *(float4*)&sW[kr * 128 + c4] = *(const float4*)&W[(size_t)(kk + kr) * DD + c4];
        }
        __syncthreads();
#pragma unroll
        for (int k2 = 0; k2 < 16; k2++) {
            float4 a0 = *(float4*)&sA[k2 * 132 + ty * 8];
            float4 a1 = *(float4*)&sA[k2 * 132 + ty * 8 + 4];
            const float* wr = &sW[k2 * 128];
            float4 w0 = *(const float4*)&wr[tx * 4];
            float4 w1 = *(const float4*)&wr[64 + tx * 4];
            float av[8] = {a0.x, a0.y, a0.z, a0.w, a1.x, a1.y, a1.z, a1.w};
            float wv[8] = {w0.x, w0.y, w0.z, w0.w, w1.x, w1.y, w1.z, w1.w};
#pragma unroll
            for (int m = 0; m < 8; m++)
#pragma unroll
                for (int n = 0; n < 8; n++)
                    acc[m][n] = fmaf(av[m], wv[n], acc[m][n]);
        }
    }
#pragma unroll
    for (int m = 0; m < 8; m++) {
        int gr = r0 + ty * 8 + m;
        if (gr < NN) {
            *(float4*)&C[(size_t)gr * DD + tx * 4] =
                make_float4(acc[m][0], acc[m][1], acc[m][2], acc[m][3]);
            *(float4*)&C[(size_t)gr * DD + 64 + tx * 4] =
                make_float4(acc[m][4], acc[m][5], acc[m][6], acc[m][7]);
        }
    }
}

// ---------------- fused loss: one warp per (user,item) pair ----------------
__device__ __forceinline__ float dot4(float4 a, float4 b) {
    return a.x * b.x + a.y * b.y + a.z * b.z + a.w * b.w;
}

__global__ void k_loss(const float* __restrict__ enc,
                       const int* __restrict__ user, const int* __restrict__ item,
                       const int* __restrict__ labels,
                       const float* __restrict__ clsW, const float* __restrict__ clsB,
                       const float* __restrict__ duW, const float* __restrict__ duB,
                       const float* __restrict__ diW, const float* __restrict__ diB,
                       const int* __restrict__ numUser, int accBase) {
    __shared__ float sb[8], su[8], si[8];
    int tid = threadIdx.x;
    int wid = tid >> 5, lane = tid & 31;
    int b = blockIdx.x * 8 + wid;
    float bce = 0.f, cu = 0.f, ci = 0.f;
    if (b < BB) {
        int nu = numUser ? numUser[0] : 50000;
        int u = user[b];
        int it = item[b] + nu;
        float4 uf = ((const float4*)enc)[u * 32 + lane];
        float4 vf = ((const float4*)enc)[it * 32 + lane];
        float4 cwu = ((const float4*)clsW)[lane];
        float4 cwi = ((const float4*)clsW)[32 + lane];
        float4 dw = ((const float4*)duW)[lane];
        float4 iw = ((const float4*)diW)[lane];
        float z = dot4(uf, cwu) + dot4(vf, cwi);
        float zu = dot4(uf, dw);
        float zi = dot4(vf, iw);
#pragma unroll
        for (int o = 16; o; o >>= 1) {
            z  += __shfl_xor_sync(0xffffffffu, z, o);
            zu += __shfl_xor_sync(0xffffffffu, zu, o);
            zi += __shfl_xor_sync(0xffffffffu, zi, o);
        }
        z += clsB[0];
        zu += duB[0];
        zi += diB[0];
        float y = (float)labels[b];
        float sp_pos = log1pf(expf(-fabsf(z))) + fmaxf(z, 0.f);  // softplus(z)
        float sp_neg = sp_pos - z;                               // softplus(-z)
        bce = y * sp_neg + (1.f - y) * sp_pos;
        cu = 1.f / (1.f + expf(-zu));
        ci = 1.f / (1.f + expf(-zi));
    }
    if (lane == 0) { sb[wid] = bce; su[wid] = cu; si[wid] = ci; }
    __syncthreads();
    if (tid == 0) {
        float B_ = 0.f, U = 0.f, I = 0.f;
#pragma unroll
        for (int i = 0; i < 8; i++) { B_ += sb[i]; U += su[i]; I += si[i]; }
        atomicAdd(&g_acc[accBase + 0], (double)B_);
        atomicAdd(&g_acc[accBase + 1], (double)U);
        atomicAdd(&g_acc[accBase + 2], (double)I);
    }
}

__global__ void k_final(float* out) {
    double invB = 1.0 / (double)BB;
    double clf = (g_acc[0] + g_acc[3]) * invB;
    double dom = fabs(g_acc[1] - g_acc[4]) * invB + fabs(g_acc[2] - g_acc[5]) * invB;
    out[0] = (float)(clf + dom);
}

// ---------------- launch ----------------
extern "C" void kernel_launch(void* const* d_in, const int* in_sizes, int n_in,
                              void* d_out, int out_size) {
    const float* feats_s = (const float*)d_in[0];
    const float* feats_t = (const float*)d_in[1];
    const float* W1 = (const float*)d_in[2];
    const float* b1 = (const float*)d_in[3];
    const float* W2 = (const float*)d_in[4];
    const float* b2 = (const float*)d_in[5];
    const float* clsW = (const float*)d_in[6];
    const float* clsB = (const float*)d_in[7];
    const float* duW = (const float*)d_in[8];
    const float* duB = (const float*)d_in[9];
    const float* diW = (const float*)d_in[10];
    const float* diB = (const float*)d_in[11];
    const int* es[2] = {(const int*)d_in[12], (const int*)d_in[14]};
    const int* ed[2] = {(const int*)d_in[13], (const int*)d_in[15]};
    const int* user[2] = {(const int*)d_in[16], (const int*)d_in[19]};
    const int* item[2] = {(const int*)d_in[17], (const int*)d_in[20]};
    const int* lab[2]  = {(const int*)d_in[18], (const int*)d_in[21]};
    const int* nu[2]   = {(n_in > 22) ? (const int*)d_in[22] : (const int*)0,
                          (n_in > 23) ? (const int*)d_in[23] : (const int*)0};
    const float* feats[2] = {feats_s, feats_t};
    float* out = (float*)d_out;

    float* tmp; float* h;
    cudaGetSymbolAddress((void**)&tmp, g_tmp);
    cudaGetSymbolAddress((void**)&h, g_h);

    const int TB = 256;
    for (int dom = 0; dom < 2; dom++) {
        k_zero<<<(NN + TB - 1) / TB, TB>>>(dom == 0 ? 1 : 0);
        k_deg<<<(EE + TB - 1) / TB, TB>>>(ed[dom]);
        k_dinv<<<(NN + TB - 1) / TB, TB>>>();

        // layer 1
        k_gemm<false><<<(NN + 127) / 128, 256>>>(feats[dom], W1, tmp);
        k_init<<<(NN * 32 + TB - 1) / TB, TB>>>(tmp, b1, h);
        k_scatter<<<EE / 8, 256>>>(tmp, es[dom], ed[dom], h);

        // layer 2 (relu folded into GEMM A-load)
        k_gemm<true><<<(NN + 127) / 128, 256>>>(h, W2, tmp);
        k_init<<<(NN * 32 + TB - 1) / TB, TB>>>(tmp, b2, h);
        k_scatter<<<EE / 8, 256>>>(tmp, es[dom], ed[dom], h);

        // losses for this domain
        k_loss<<<(BB + 7) / 8, 256>>>(h, user[dom], item[dom], lab[dom],
                                      clsW, clsB, duW, duB, diW, diB,
                                      nu[dom], dom * 3);
    }
    k_final<<<1, 1>>>(out);
}

// round 2
// speedup vs baseline: 1.4051x; 1.4051x over previous
#include <cuda_runtime.h>
#include <math.h>

#define NN 100000
#define DD 128
#define EE 1600000
#define BB 100000

// ---------------- scratch (no allocations allowed) ----------------
__device__ float  g_tmp[(size_t)NN * DD];   // X@W / H@W scratch
__device__ float  g_h[(size_t)NN * DD];     // layer output / encoding
__device__ float  g_dinv[NN];
__device__ int    g_deg[NN];
__device__ int    g_rowptr[NN + 1];
__device__ int    g_cursor[NN];
__device__ int    g_col[EE];
__device__ double g_acc[8];                 // [bce_s, cu_s, ci_s, bce_t, cu_t, ci_t]

// ---------------- degree / CSR build ----------------
__global__ void k_zero(int zero_acc) {
    int i = blockIdx.x * blockDim.x + threadIdx.x;
    if (i < NN) g_deg[i] = 0;
    if (zero_acc && i < 8) g_acc[i] = 0.0;
}

__global__ void k_deg(const int* __restrict__ dst) {
    int e = blockIdx.x * blockDim.x + threadIdx.x;
    if (e < EE) atomicAdd(&g_deg[dst[e]], 1);
}

// single-block exclusive scan of g_deg -> g_rowptr (1024 threads)
__global__ void k_scan() {
    __shared__ int s_warp[32];
    __shared__ int s_carry;
    int tid = threadIdx.x;
    int lane = tid & 31, wid = tid >> 5;
    if (tid == 0) s_carry = 0;
    __syncthreads();
    for (int base = 0; base < NN; base += 1024) {
        int i = base + tid;
        int v = (i < NN) ? g_deg[i] : 0;
        // warp inclusive scan
        int x = v;
#pragma unroll
        for (int o = 1; o < 32; o <<= 1) {
            int y = __shfl_up_sync(0xffffffffu, x, o);
            if (lane >= o) x += y;
        }
        if (lane == 31) s_warp[wid] = x;
        __syncthreads();
        if (wid == 0) {
            int w = s_warp[lane];
#pragma unroll
            for (int o = 1; o < 32; o <<= 1) {
                int y = __shfl_up_sync(0xffffffffu, w, o);
                if (lane >= o) w += y;
            }
            s_warp[lane] = w;
        }
        __syncthreads();
        int carry = s_carry;
        int excl = carry + (wid ? s_warp[wid - 1] : 0) + x - v;
        if (i < NN) {
            g_rowptr[i] = excl;
            g_cursor[i] = excl;
        }
        __syncthreads();
        if (tid == 1023) s_carry = carry + s_warp[31];
        __syncthreads();
    }
    if (tid == 0) g_rowptr[NN] = s_carry;
}

__global__ void k_dinv() {
    int i = blockIdx.x * blockDim.x + threadIdx.x;
    if (i < NN) g_dinv[i] = rsqrtf((float)g_deg[i] + 1.0f);  // +1 = self loop
}

__global__ void k_fill(const int* __restrict__ src, const int* __restrict__ dst) {
    int e = blockIdx.x * blockDim.x + threadIdx.x;
    if (e < EE) {
        int pos = atomicAdd(&g_cursor[dst[e]], 1);
        g_col[pos] = src[e];
    }
}

// ---------------- gather aggregation (fuses init: bias + self-loop) ----------
// one warp per dst node: out[i] = b + dinv_i^2*tmp[i] + dinv_i * sum_j dinv_j*tmp[j]
__global__ __launch_bounds__(256) void k_gather(const float* __restrict__ tmp,
                                                const float* __restrict__ bias,
                                                float* __restrict__ out) {
    int node = blockIdx.x * 8 + (threadIdx.x >> 5);
    int lane = threadIdx.x & 31;
    if (node >= NN) return;
    int beg = g_rowptr[node];
    int end = g_rowptr[node + 1];
    const float4* tmp4 = (const float4*)tmp;
    float4 acc = make_float4(0.f, 0.f, 0.f, 0.f);
    for (int base = beg; base < end; base += 32) {
        int n = min(32, end - base);
        int s = (lane < n) ? g_col[base + lane] : 0;
        float ds = (lane < n) ? g_dinv[s] : 0.f;
        for (int i = 0; i < n; i++) {
            int sj = __shfl_sync(0xffffffffu, s, i);
            float dj = __shfl_sync(0xffffffffu, ds, i);
            float4 v = tmp4[sj * 32 + lane];
            acc.x = fmaf(dj, v.x, acc.x);
            acc.y = fmaf(dj, v.y, acc.y);
            acc.z = fmaf(dj, v.z, acc.z);
            acc.w = fmaf(dj, v.w, acc.w);
        }
    }
    float di = g_dinv[node];
    float d2 = di * di;
    float4 t = tmp4[node * 32 + lane];
    float4 b = ((const float4*)bias)[lane];
    float4 o;
    o.x = b.x + d2 * t.x + di * acc.x;
    o.y = b.y + d2 * t.y + di * acc.y;
    o.z = b.z + d2 * t.z + di * acc.z;
    o.w = b.w + d2 * t.w + di * acc.w;
    ((float4*)out)[node * 32 + lane] = o;
}

// ---------------- GEMM: C[N,128] = (relu?)A[N,128] @ W[128,128] ----------------
template <bool RELU>
__global__ __launch_bounds__(256, 2) void k_gemm(const float* __restrict__ A,
                                                 const float* __restrict__ W,
                                                 float* __restrict__ C) {
    __shared__ float sW[16 * 128];   // k-chunk of W
    __shared__ float sA[16 * 132];   // transposed A chunk [k][row], padded stride
    int tid = threadIdx.x;
    int r0 = blockIdx.x * 128;
    int tx = tid & 15, ty = tid >> 4;

    float acc[8][8];
#pragma unroll
    for (int m = 0; m < 8; m++)
#pragma unroll
        for (int n = 0; n < 8; n++) acc[m][n] = 0.f;

    for (int kk = 0; kk < DD; kk += 16) {
        __syncthreads();
#pragma unroll
        for (int i = 0; i < 2; i++) {
            int q = tid + 256 * i;
            int row = q >> 2;
            int c4 = (q & 3) << 2;
            int gr = r0 + row;
            float4 a = make_float4(0.f, 0.f, 0.f, 0.f);
            if (gr < NN) a = *(const float4*)&A[(size_t)gr * DD + kk + c4];
            if (RELU) {
                a.x = fmaxf(a.x, 0.f); a.y = fmaxf(a.y, 0.f);
                a.z = fmaxf(a.z, 0.f); a.w = fmaxf(a.w, 0.f);
            }
            sA[(c4 + 0) * 132 + row] = a.x;
            sA[(c4 + 1) * 132 + row] = a.y;
            sA[(c4 + 2) * 132 + row] = a.z;
            sA[(c4 + 3) * 132 + row] = a.w;
        }
#pragma unroll
        for (int i = 0; i < 2; i++) {
            int q = tid + 256 * i;
            int kr = q >> 5;
            int c4 = (q & 31) << 2;
            *(float4*)&sW[kr * 128 + c4] = *(const float4*)&W[(size_t)(kk + kr) * DD + c4];
        }
        __syncthreads();
#pragma unroll
        for (int k2 = 0; k2 < 16; k2++) {
            float4 a0 = *(float4*)&sA[k2 * 132 + ty * 8];
            float4 a1 = *(float4*)&sA[k2 * 132 + ty * 8 + 4];
            const float* wr = &sW[k2 * 128];
            float4 w0 = *(const float4*)&wr[tx * 4];
            float4 w1 = *(const float4*)&wr[64 + tx * 4];
            float av[8] = {a0.x, a0.y, a0.z, a0.w, a1.x, a1.y, a1.z, a1.w};
            float wv[8] = {w0.x, w0.y, w0.z, w0.w, w1.x, w1.y, w1.z, w1.w};
#pragma unroll
            for (int m = 0; m < 8; m++)
#pragma unroll
                for (int n = 0; n < 8; n++)
                    acc[m][n] = fmaf(av[m], wv[n], acc[m][n]);
        }
    }
#pragma unroll
    for (int m = 0; m < 8; m++) {
        int gr = r0 + ty * 8 + m;
        if (gr < NN) {
            *(float4*)&C[(size_t)gr * DD + tx * 4] =
                make_float4(acc[m][0], acc[m][1], acc[m][2], acc[m][3]);
            *(float4*)&C[(size_t)gr * DD + 64 + tx * 4] =
                make_float4(acc[m][4], acc[m][5], acc[m][6], acc[m][7]);
        }
    }
}

// ---------------- fused loss: one warp per (user,item) pair ----------------
__device__ __forceinline__ float dot4(float4 a, float4 b) {
    return a.x * b.x + a.y * b.y + a.z * b.z + a.w * b.w;
}

__global__ void k_loss(const float* __restrict__ enc,
                       const int* __restrict__ user, const int* __restrict__ item,
                       const int* __restrict__ labels,
                       const float* __restrict__ clsW, const float* __restrict__ clsB,
                       const float* __restrict__ duW, const float* __restrict__ duB,
                       const float* __restrict__ diW, const float* __restrict__ diB,
                       const int* __restrict__ numUser, int accBase) {
    __shared__ float sb[8], su[8], si[8];
    int tid = threadIdx.x;
    int wid = tid >> 5, lane = tid & 31;
    int b = blockIdx.x * 8 + wid;
    float bce = 0.f, cu = 0.f, ci = 0.f;
    if (b < BB) {
        int nu = numUser ? numUser[0] : 50000;
        int u = user[b];
        int it = item[b] + nu;
        float4 uf = ((const float4*)enc)[u * 32 + lane];
        float4 vf = ((const float4*)enc)[it * 32 + lane];
        float4 cwu = ((const float4*)clsW)[lane];
        float4 cwi = ((const float4*)clsW)[32 + lane];
        float4 dw = ((const float4*)duW)[lane];
        float4 iw = ((const float4*)diW)[lane];
        float z = dot4(uf, cwu) + dot4(vf, cwi);
        float zu = dot4(uf, dw);
        float zi = dot4(vf, iw);
#pragma unroll
        for (int o = 16; o; o >>= 1) {
            z  += __shfl_xor_sync(0xffffffffu, z, o);
            zu += __shfl_xor_sync(0xffffffffu, zu, o);
            zi += __shfl_xor_sync(0xffffffffu, zi, o);
        }
        z += clsB[0];
        zu += duB[0];
        zi += diB[0];
        float y = (float)labels[b];
        float sp_pos = log1pf(expf(-fabsf(z))) + fmaxf(z, 0.f);  // softplus(z)
        float sp_neg = sp_pos - z;                               // softplus(-z)
        bce = y * sp_neg + (1.f - y) * sp_pos;
        cu = 1.f / (1.f + expf(-zu));
        ci = 1.f / (1.f + expf(-zi));
    }
    if (lane == 0) { sb[wid] = bce; su[wid] = cu; si[wid] = ci; }
    __syncthreads();
    if (tid == 0) {
        float B_ = 0.f, U = 0.f, I = 0.f;
#pragma unroll
        for (int i = 0; i < 8; i++) { B_ += sb[i]; U += su[i]; I += si[i]; }
        atomicAdd(&g_acc[accBase + 0], (double)B_);
        atomicAdd(&g_acc[accBase + 1], (double)U);
        atomicAdd(&g_acc[accBase + 2], (double)I);
    }
}

__global__ void k_final(float* out) {
    double invB = 1.0 / (double)BB;
    double clf = (g_acc[0] + g_acc[3]) * invB;
    double dom = fabs(g_acc[1] - g_acc[4]) * invB + fabs(g_acc[2] - g_acc[5]) * invB;
    out[0] = (float)(clf + dom);
}

// ---------------- launch ----------------
extern "C" void kernel_launch(void* const* d_in, const int* in_sizes, int n_in,
                              void* d_out, int out_size) {
    const float* feats_s = (const float*)d_in[0];
    const float* feats_t = (const float*)d_in[1];
    const float* W1 = (const float*)d_in[2];
    const float* b1 = (const float*)d_in[3];
    const float* W2 = (const float*)d_in[4];
    const float* b2 = (const float*)d_in[5];
    const float* clsW = (const float*)d_in[6];
    const float* clsB = (const float*)d_in[7];
    const float* duW = (const float*)d_in[8];
    const float* duB = (const float*)d_in[9];
    const float* diW = (const float*)d_in[10];
    const float* diB = (const float*)d_in[11];
    const int* es[2] = {(const int*)d_in[12], (const int*)d_in[14]};
    const int* ed[2] = {(const int*)d_in[13], (const int*)d_in[15]};
    const int* user[2] = {(const int*)d_in[16], (const int*)d_in[19]};
    const int* item[2] = {(const int*)d_in[17], (const int*)d_in[20]};
    const int* lab[2]  = {(const int*)d_in[18], (const int*)d_in[21]};
    const int* nu[2]   = {(n_in > 22) ? (const int*)d_in[22] : (const int*)0,
                          (n_in > 23) ? (const int*)d_in[23] : (const int*)0};
    const float* feats[2] = {feats_s, feats_t};
    float* out = (float*)d_out;

    float* tmp; float* h;
    cudaGetSymbolAddress((void**)&tmp, g_tmp);
    cudaGetSymbolAddress((void**)&h, g_h);

    const int TB = 256;
    for (int dom = 0; dom < 2; dom++) {
        // CSR build (by dst) + dinv
        k_zero<<<(NN + TB - 1) / TB, TB>>>(dom == 0 ? 1 : 0);
        k_deg<<<(EE + TB - 1) / TB, TB>>>(ed[dom]);
        k_scan<<<1, 1024>>>();
        k_dinv<<<(NN + TB - 1) / TB, TB>>>();
        k_fill<<<(EE + TB - 1) / TB, TB>>>(es[dom], ed[dom]);

        // layer 1
        k_gemm<false><<<(NN + 127) / 128, 256>>>(feats[dom], W1, tmp);
        k_gather<<<(NN + 7) / 8, 256>>>(tmp, b1, h);

        // layer 2 (relu folded into GEMM A-load)
        k_gemm<true><<<(NN + 127) / 128, 256>>>(h, W2, tmp);
        k_gather<<<(NN + 7) / 8, 256>>>(tmp, b2, h);

        // losses for this domain
        k_loss<<<(BB + 7) / 8, 256>>>(h, user[dom], item[dom], lab[dom],
                                      clsW, clsB, duW, duB, diW, diB,
                                      nu[dom], dom * 3);
    }
    k_final<<<1, 1>>>(out);
}

// round 3
// speedup vs baseline: 1.9921x; 1.4178x over previous
#include <cuda_runtime.h>
#include <cuda_fp16.h>
#include <math.h>

#define NN 100000
#define DD 128
#define EE 1600000
#define BB 100000

// ---------------- scratch (no allocations allowed) ----------------
__device__ __align__(16) __half g_tmph[(size_t)NN * DD]; // dinv-scaled GEMM out (fp16)
__device__ __align__(16) float  g_h[(size_t)NN * DD];    // layer output / encoding
__device__ float  g_dinv[NN];
__device__ int    g_deg[NN];
__device__ int    g_rowptr[NN + 1];
__device__ int    g_cursor[NN];
__device__ int    g_col[EE];
__device__ int    g_bsum[128];
__device__ int    g_boff[128];
__device__ double g_acc[8];                 // [bce_s, cu_s, ci_s, bce_t, cu_t, ci_t]

// ---------------- degree / CSR build ----------------
__global__ void k_zero(int zero_acc) {
    int i = blockIdx.x * blockDim.x + threadIdx.x;
    if (i < NN) g_deg[i] = 0;
    if (zero_acc && i < 8) g_acc[i] = 0.0;
}

__global__ void k_deg(const int* __restrict__ dst) {
    int e = blockIdx.x * blockDim.x + threadIdx.x;
    if (e < EE) atomicAdd(&g_deg[dst[e]], 1);
}

// phase 1: per-block (1024) exclusive scan; local prefix -> rowptr, block total -> bsum
__global__ void k_scan1() {
    __shared__ int s_warp[32];
    int tid = threadIdx.x;
    int lane = tid & 31, wid = tid >> 5;
    int i = blockIdx.x * 1024 + tid;
    int v = (i < NN) ? g_deg[i] : 0;
    int x = v;
#pragma unroll
    for (int o = 1; o < 32; o <<= 1) {
        int y = __shfl_up_sync(0xffffffffu, x, o);
        if (lane >= o) x += y;
    }
    if (lane == 31) s_warp[wid] = x;
    __syncthreads();
    if (wid == 0) {
        int w = s_warp[lane];
#pragma unroll
        for (int o = 1; o < 32; o <<= 1) {
            int y = __shfl_up_sync(0xffffffffu, w, o);
            if (lane >= o) w += y;
        }
        s_warp[lane] = w;
    }
    __syncthreads();
    int excl = (wid ? s_warp[wid - 1] : 0) + x - v;
    if (i < NN) g_rowptr[i] = excl;
    if (tid == 1023) g_bsum[blockIdx.x] = s_warp[31];
}

// phase 2: single warp scans the 98 block sums
__global__ void k_scan2(int nblk) {
    int lane = threadIdx.x;
    int carry = 0;
    for (int base = 0; base < nblk; base += 32) {
        int idx = base + lane;
        int v = (idx < nblk) ? g_bsum[idx] : 0;
        int x = v;
#pragma unroll
        for (int o = 1; o < 32; o <<= 1) {
            int y = __shfl_up_sync(0xffffffffu, x, o);
            if (lane >= o) x += y;
        }
        if (idx < nblk) g_boff[idx] = carry + x - v;
        carry += __shfl_sync(0xffffffffu, x, 31);
    }
    if (lane == 0) g_rowptr[NN] = carry;
}

// phase 3: add block offsets; init cursor + dinv
__global__ void k_scan3() {
    int i = blockIdx.x * blockDim.x + threadIdx.x;
    if (i < NN) {
        int r = g_rowptr[i] + g_boff[i >> 10];
        g_rowptr[i] = r;
        g_cursor[i] = r;
        g_dinv[i] = rsqrtf((float)g_deg[i] + 1.0f);  // +1 = self loop
    }
}

__global__ void k_fill(const int* __restrict__ src, const int* __restrict__ dst) {
    int e = blockIdx.x * blockDim.x + threadIdx.x;
    if (e < EE) {
        int pos = atomicAdd(&g_cursor[dst[e]], 1);
        g_col[pos] = src[e];
    }
}

// ---------------- gather aggregation ------------------------------------
// tmp' rows are pre-scaled by dinv[row] (done in GEMM epilogue), fp16.
// out[i] = b + dinv_i * (tmp'[i] + sum_j tmp'[j])
__device__ __forceinline__ void acc_row(const uint2* __restrict__ t2, int row, int lane,
                                        float4& acc) {
    uint2 u = t2[row * 32 + lane];
    float2 fa = __half22float2(*(__half2*)&u.x);
    float2 fb = __half22float2(*(__half2*)&u.y);
    acc.x += fa.x; acc.y += fa.y; acc.z += fb.x; acc.w += fb.y;
}

__global__ __launch_bounds__(256) void k_gather(const __half* __restrict__ tmp,
                                                const float* __restrict__ bias,
                                                float* __restrict__ out) {
    int node = blockIdx.x * 8 + (threadIdx.x >> 5);
    int lane = threadIdx.x & 31;
    if (node >= NN) return;
    int beg = g_rowptr[node];
    int end = g_rowptr[node + 1];
    const uint2* t2 = (const uint2*)tmp;
    float4 acc = make_float4(0.f, 0.f, 0.f, 0.f);
    for (int base = beg; base < end; base += 32) {
        int n = min(32, end - base);
        int s = (lane < n) ? g_col[base + lane] : 0;
        int i = 0;
        for (; i + 4 <= n; i += 4) {
            int a = __shfl_sync(0xffffffffu, s, i);
            int b = __shfl_sync(0xffffffffu, s, i + 1);
            int c = __shfl_sync(0xffffffffu, s, i + 2);
            int d = __shfl_sync(0xffffffffu, s, i + 3);
            acc_row(t2, a, lane, acc);
            acc_row(t2, b, lane, acc);
            acc_row(t2, c, lane, acc);
            acc_row(t2, d, lane, acc);
        }
        for (; i < n; i++) {
            int a = __shfl_sync(0xffffffffu, s, i);
            acc_row(t2, a, lane, acc);
        }
    }
    acc_row(t2, node, lane, acc);   // self-loop term (tmp' already dinv-scaled)
    float di = g_dinv[node];
    float4 b = ((const float4*)bias)[lane];
    float4 o;
    o.x = fmaf(di, acc.x, b.x);
    o.y = fmaf(di, acc.y, b.y);
    o.z = fmaf(di, acc.z, b.z);
    o.w = fmaf(di, acc.w, b.w);
    ((float4*)out)[node * 32 + lane] = o;
}

// ------- GEMM: C_half[r,:] = dinv[r] * ((relu?)A[r,:] @ W) ----------------
template <bool RELU>
__global__ __launch_bounds__(256, 2) void k_gemm(const float* __restrict__ A,
                                                 const float* __restrict__ W,
                                                 __half* __restrict__ C) {
    __shared__ float sW[16 * 128];
    __shared__ float sA[16 * 132];
    int tid = threadIdx.x;
    int r0 = blockIdx.x * 128;
    int tx = tid & 15, ty = tid >> 4;

    float acc[8][8];
#pragma unroll
    for (int m = 0; m < 8; m++)
#pragma unroll
        for (int n = 0; n < 8; n++) acc[m][n] = 0.f;

    for (int kk = 0; kk < DD; kk += 16) {
        __syncthreads();
#pragma unroll
        for (int i = 0; i < 2; i++) {
            int q = tid + 256 * i;
            int row = q >> 2;
            int c4 = (q & 3) << 2;
            int gr = r0 + row;
            float4 a = make_float4(0.f, 0.f, 0.f, 0.f);
            if (gr < NN) a = *(const float4*)&A[(size_t)gr * DD + kk + c4];
            if (RELU) {
                a.x = fmaxf(a.x, 0.f); a.y = fmaxf(a.y, 0.f);
                a.z = fmaxf(a.z, 0.f); a.w = fmaxf(a.w, 0.f);
            }
            sA[(c4 + 0) * 132 + row] = a.x;
            sA[(c4 + 1) * 132 + row] = a.y;
            sA[(c4 + 2) * 132 + row] = a.z;
            sA[(c4 + 3) * 132 + row] = a.w;
        }
#pragma unroll
        for (int i = 0; i < 2; i++) {
            int q = tid + 256 * i;
            int kr = q >> 5;
            int c4 = (q & 31) << 2;
            *(float4*)&sW[kr * 128 + c4] = *(const float4*)&W[(size_t)(kk + kr) * DD + c4];
        }
        __syncthreads();
#pragma unroll
        for (int k2 = 0; k2 < 16; k2++) {
            float4 a0 = *(float4*)&sA[k2 * 132 + ty * 8];
            float4 a1 = *(float4*)&sA[k2 * 132 + ty * 8 + 4];
            const float* wr = &sW[k2 * 128];
            float4 w0 = *(const float4*)&wr[tx * 4];
            float4 w1 = *(const float4*)&wr[64 + tx * 4];
            float av[8] = {a0.x, a0.y, a0.z, a0.w, a1.x, a1.y, a1.z, a1.w};
            float wv[8] = {w0.x, w0.y, w0.z, w0.w, w1.x, w1.y, w1.z, w1.w};
#pragma unroll
            for (int m = 0; m < 8; m++)
#pragma unroll
                for (int n = 0; n < 8; n++)
                    acc[m][n] = fmaf(av[m], wv[n], acc[m][n]);
        }
    }
#pragma unroll
    for (int m = 0; m < 8; m++) {
        int gr = r0 + ty * 8 + m;
        if (gr < NN) {
            float di = g_dinv[gr];
            uint2 u0, u1;
            __half2 h;
            h = __floats2half2_rn(acc[m][0] * di, acc[m][1] * di); u0.x = *(unsigned*)&h;
            h = __floats2half2_rn(acc[m][2] * di, acc[m][3] * di); u0.y = *(unsigned*)&h;
            h = __floats2half2_rn(acc[m][4] * di, acc[m][5] * di); u1.x = *(unsigned*)&h;
            h = __floats2half2_rn(acc[m][6] * di, acc[m][7] * di); u1.y = *(unsigned*)&h;
            *(uint2*)&C[(size_t)gr * DD + tx * 4] = u0;
            *(uint2*)&C[(size_t)gr * DD + 64 + tx * 4] = u1;
        }
    }
}

// ---------------- fused loss: one warp per (user,item) pair ----------------
__device__ __forceinline__ float dot4(float4 a, float4 b) {
    return a.x * b.x + a.y * b.y + a.z * b.z + a.w * b.w;
}

__global__ void k_loss(const float* __restrict__ enc,
                       const int* __restrict__ user, const int* __restrict__ item,
                       const int* __restrict__ labels,
                       const float* __restrict__ clsW, const float* __restrict__ clsB,
                       const float* __restrict__ duW, const float* __restrict__ duB,
                       const float* __restrict__ diW, const float* __restrict__ diB,
                       const int* __restrict__ numUser, int accBase) {
    __shared__ float sb[8], su[8], si[8];
    int tid = threadIdx.x;
    int wid = tid >> 5, lane = tid & 31;
    int b = blockIdx.x * 8 + wid;
    float bce = 0.f, cu = 0.f, ci = 0.f;
    if (b < BB) {
        int nu = numUser ? numUser[0] : 50000;
        int u = user[b];
        int it = item[b] + nu;
        float4 uf = ((const float4*)enc)[u * 32 + lane];
        float4 vf = ((const float4*)enc)[it * 32 + lane];
        float4 cwu = ((const float4*)clsW)[lane];
        float4 cwi = ((const float4*)clsW)[32 + lane];
        float4 dw = ((const float4*)duW)[lane];
        float4 iw = ((const float4*)diW)[lane];
        float z = dot4(uf, cwu) + dot4(vf, cwi);
        float zu = dot4(uf, dw);
        float zi = dot4(vf, iw);
#pragma unroll
        for (int o = 16; o; o >>= 1) {
            z  += __shfl_xor_sync(0xffffffffu, z, o);
            zu += __shfl_xor_sync(0xffffffffu, zu, o);
            zi += __shfl_xor_sync(0xffffffffu, zi, o);
        }
        z += clsB[0];
        zu += duB[0];
        zi += diB[0];
        float y = (float)labels[b];
        float sp_pos = log1pf(expf(-fabsf(z))) + fmaxf(z, 0.f);  // softplus(z)
        float sp_neg = sp_pos - z;                               // softplus(-z)
        bce = y * sp_neg + (1.f - y) * sp_pos;
        cu = 1.f / (1.f + expf(-zu));
        ci = 1.f / (1.f + expf(-zi));
    }
    if (lane == 0) { sb[wid] = bce; su[wid] = cu; si[wid] = ci; }
    __syncthreads();
    if (tid == 0) {
        float B_ = 0.f, U = 0.f, I = 0.f;
#pragma unroll
        for (int i = 0; i < 8; i++) { B_ += sb[i]; U += su[i]; I += si[i]; }
        atomicAdd(&g_acc[accBase + 0], (double)B_);
        atomicAdd(&g_acc[accBase + 1], (double)U);
        atomicAdd(&g_acc[accBase + 2], (double)I);
    }
}

__global__ void k_final(float* out) {
    double invB = 1.0 / (double)BB;
    double clf = (g_acc[0] + g_acc[3]) * invB;
    double dom = fabs(g_acc[1] - g_acc[4]) * invB + fabs(g_acc[2] - g_acc[5]) * invB;
    out[0] = (float)(clf + dom);
}

// ---------------- launch ----------------
extern "C" void kernel_launch(void* const* d_in, const int* in_sizes, int n_in,
                              void* d_out, int out_size) {
    const float* feats_s = (const float*)d_in[0];
    const float* feats_t = (const float*)d_in[1];
    const float* W1 = (const float*)d_in[2];
    const float* b1 = (const float*)d_in[3];
    const float* W2 = (const float*)d_in[4];
    const float* b2 = (const float*)d_in[5];
    const float* clsW = (const float*)d_in[6];
    const float* clsB = (const float*)d_in[7];
    const float* duW = (const float*)d_in[8];
    const float* duB = (const float*)d_in[9];
    const float* diW = (const float*)d_in[10];
    const float* diB = (const float*)d_in[11];
    const int* es[2] = {(const int*)d_in[12], (const int*)d_in[14]};
    const int* ed[2] = {(const int*)d_in[13], (const int*)d_in[15]};
    const int* user[2] = {(const int*)d_in[16], (const int*)d_in[19]};
    const int* item[2] = {(const int*)d_in[17], (const int*)d_in[20]};
    const int* lab[2]  = {(const int*)d_in[18], (const int*)d_in[21]};
    const int* nu[2]   = {(n_in > 22) ? (const int*)d_in[22] : (const int*)0,
                          (n_in > 23) ? (const int*)d_in[23] : (const int*)0};
    const float* feats[2] = {feats_s, feats_t};
    float* out = (float*)d_out;

    __half* tmp; float* h;
    cudaGetSymbolAddress((void**)&tmp, g_tmph);
    cudaGetSymbolAddress((void**)&h, g_h);

    const int TB = 256;
    const int NBLK = (NN + 1023) / 1024;   // 98
    for (int dom = 0; dom < 2; dom++) {
        // CSR build (by dst) + dinv
        k_zero<<<(NN + TB - 1) / TB, TB>>>(dom == 0 ? 1 : 0);
        k_deg<<<(EE + TB - 1) / TB, TB>>>(ed[dom]);
        k_scan1<<<NBLK, 1024>>>();
        k_scan2<<<1, 32>>>(NBLK);
        k_scan3<<<(NN + TB - 1) / TB, TB>>>();
        k_fill<<<(EE + TB - 1) / TB, TB>>>(es[dom], ed[dom]);

        // layer 1
        k_gemm<false><<<(NN + 127) / 128, 256>>>(feats[dom], W1, tmp);
        k_gather<<<(NN + 7) / 8, 256>>>(tmp, b1, h);

        // layer 2 (relu folded into GEMM A-load)
        k_gemm<true><<<(NN + 127) / 128, 256>>>(h, W2, tmp);
        k_gather<<<(NN + 7) / 8, 256>>>(tmp, b2, h);

        // losses for this domain
        k_loss<<<(BB + 7) / 8, 256>>>(h, user[dom], item[dom], lab[dom],
                                      clsW, clsB, duW, duB, diW, diB,
                                      nu[dom], dom * 3);
    }
    k_final<<<1, 1>>>(out);
}